// round 3
// baseline (speedup 1.0000x reference)
#include <cuda_runtime.h>
#include <stdint.h>

#define HD 256
#define NB 16
#define NFQ 1024
#define NGK 2048

// ---------------- scratch (device globals; no allocation allowed) ----------
static __device__ float g_x[NB * NFQ * HD];            //  16 MB current x
static __device__ float g_q[NB * NFQ * HD];            //  16 MB
static __device__ float g_k[NB * NGK * HD];            //  33 MB
static __device__ float g_v[NB * NGK * HD];            //  33 MB
static __device__ float g_s[(size_t)NB * NFQ * NGK];   // 134 MB scores
static __device__ float g_a[NB * NFQ * HD];            //  16 MB attn out
static __device__ float g_weff[12 * HD * HD];          // collapsed weights [t*4+l]
static __device__ float g_beff[12 * HD];               // collapsed biases
static __device__ float g_wtmp[4 * HD * HD];           // W0@W1 temp (batched over l)

// ---------------- generic tiled SGEMM ---------------------------------------
// C[M,N] = alpha * A[M,K] @ op(B) + bias, batched over blockIdx.z.
// transB==0: B is [K,N] row-major.  transB==1: B is [N,K] row-major (C=A@B^T).
__global__ __launch_bounds__(256) void gemm64(
    const float* __restrict__ A, const float* __restrict__ Bm,
    const float* __restrict__ bias, float* __restrict__ C,
    int M, int N, int K, float alpha,
    long batchA, long batchB, long batchC, int transB)
{
    __shared__ __align__(16) float As[16][64];
    __shared__ __align__(16) float Bs[16][64];

    const int tid = threadIdx.x;
    const int tx = tid & 15;   // n direction (4 cols each)
    const int ty = tid >> 4;   // m direction (4 rows each)
    const int m0 = blockIdx.y * 64;
    const int n0 = blockIdx.x * 64;

    A  += (long)blockIdx.z * batchA;
    Bm += (long)blockIdx.z * batchB;
    C  += (long)blockIdx.z * batchC;

    float acc[4][4];
#pragma unroll
    for (int i = 0; i < 4; i++)
#pragma unroll
        for (int j = 0; j < 4; j++) acc[i][j] = 0.f;

    const int a_row = tid >> 2;  // 0..63
    const int a_cg  = tid & 3;   // 0..3  (group of 4 k's)
    const int b_row = tid >> 4;  // 0..15 (NN: k row)
    const int b_cg  = tid & 15;  // 0..15 (NN: group of 4 n's)

    for (int k0 = 0; k0 < K; k0 += 16) {
        // A tile 64(m) x 16(k), stored transposed As[k][m]
        float4 av = *reinterpret_cast<const float4*>(
            A + (long)(m0 + a_row) * K + k0 + a_cg * 4);
        As[a_cg * 4 + 0][a_row] = av.x;
        As[a_cg * 4 + 1][a_row] = av.y;
        As[a_cg * 4 + 2][a_row] = av.z;
        As[a_cg * 4 + 3][a_row] = av.w;

        if (transB) {
            float4 bv = *reinterpret_cast<const float4*>(
                Bm + (long)(n0 + a_row) * K + k0 + a_cg * 4);
            Bs[a_cg * 4 + 0][a_row] = bv.x;
            Bs[a_cg * 4 + 1][a_row] = bv.y;
            Bs[a_cg * 4 + 2][a_row] = bv.z;
            Bs[a_cg * 4 + 3][a_row] = bv.w;
        } else {
            float4 bv = *reinterpret_cast<const float4*>(
                Bm + (long)(k0 + b_row) * N + n0 + b_cg * 4);
            *reinterpret_cast<float4*>(&Bs[b_row][b_cg * 4]) = bv;
        }
        __syncthreads();

#pragma unroll
        for (int kk = 0; kk < 16; kk++) {
            float4 a = *reinterpret_cast<const float4*>(&As[kk][ty << 2]);
            float4 b = *reinterpret_cast<const float4*>(&Bs[kk][tx << 2]);
            float ar[4] = {a.x, a.y, a.z, a.w};
            float br[4] = {b.x, b.y, b.z, b.w};
#pragma unroll
            for (int i = 0; i < 4; i++)
#pragma unroll
                for (int j = 0; j < 4; j++)
                    acc[i][j] = fmaf(ar[i], br[j], acc[i][j]);
        }
        __syncthreads();
    }

#pragma unroll
    for (int i = 0; i < 4; i++) {
        const int m = m0 + (ty << 2) + i;
        const int n = n0 + (tx << 2);
        float4 o;
        o.x = acc[i][0] * alpha;
        o.y = acc[i][1] * alpha;
        o.z = acc[i][2] * alpha;
        o.w = acc[i][3] * alpha;
        if (bias) {
            o.x += bias[n + 0];
            o.y += bias[n + 1];
            o.z += bias[n + 2];
            o.w += bias[n + 3];
        }
        *reinterpret_cast<float4*>(C + (long)m * N + n) = o;
    }
}

// ---------------- bias collapse: beff = (b0@W1 + b1)@W2 + b2 ---------------
__global__ __launch_bounds__(256) void bias_collapse(
    const float* __restrict__ bq, const float* __restrict__ bk,
    const float* __restrict__ bv,
    const float* __restrict__ Wq, const float* __restrict__ Wk,
    const float* __restrict__ Wv,
    float* __restrict__ beff)
{
    const int t = blockIdx.x >> 2;
    const int l = blockIdx.x & 3;
    const float* bb = (t == 0 ? bq : (t == 1 ? bk : bv)) + (size_t)l * 3 * HD;
    const float* WW = (t == 0 ? Wq : (t == 1 ? Wk : Wv)) + (size_t)l * 3 * HD * HD;
    const int n = threadIdx.x;
    __shared__ float tmp[HD];

    float s = bb[HD + n];  // b1[n]
    for (int k = 0; k < HD; k++)
        s = fmaf(bb[k], WW[HD * HD + k * HD + n], s);
    tmp[n] = s;
    __syncthreads();
    float s2 = bb[2 * HD + n];  // b2[n]
    for (int k = 0; k < HD; k++)
        s2 = fmaf(tmp[k], WW[2 * HD * HD + k * HD + n], s2);
    beff[(size_t)blockIdx.x * HD + n] = s2;
}

// ---------------- masked softmax (exact reference semantics) ---------------
// mask is int32 (harness marshals bool -> int32). one block per row.
__global__ __launch_bounds__(256) void softmax_mask_kernel(
    float* __restrict__ S, const int* __restrict__ mask, int Nk)
{
    const long row = blockIdx.x;
    float* s = S + row * (long)Nk;
    const int* mk = mask + row * (long)Nk;
    const int tid = threadIdx.x;
    const int nIter = Nk >> 8;  // 4 or 8

    float v[8];
    int m[8];
    float vmax = -3.0e38f;
#pragma unroll 8
    for (int it = 0; it < nIter; it++) {
        const int idx = it * 256 + tid;
        float sv = s[idx];
        int mm = mk[idx];
        sv = mm ? -1e12f : sv;
        v[it] = sv;
        m[it] = mm;
        vmax = fmaxf(vmax, sv);
    }

    __shared__ float red[8];
#pragma unroll
    for (int o = 16; o > 0; o >>= 1)
        vmax = fmaxf(vmax, __shfl_xor_sync(0xffffffffu, vmax, o));
    if ((tid & 31) == 0) red[tid >> 5] = vmax;
    __syncthreads();
    if (tid == 0) {
        float t = red[0];
#pragma unroll
        for (int i = 1; i < 8; i++) t = fmaxf(t, red[i]);
        red[0] = t;
    }
    __syncthreads();
    vmax = red[0];
    __syncthreads();

    float sum = 0.f;
#pragma unroll 8
    for (int it = 0; it < nIter; it++) {
        float e = __expf(v[it] - vmax);
        v[it] = e;
        sum += e;
    }
#pragma unroll
    for (int o = 16; o > 0; o >>= 1)
        sum += __shfl_xor_sync(0xffffffffu, sum, o);
    if ((tid & 31) == 0) red[tid >> 5] = sum;
    __syncthreads();
    if (tid == 0) {
        float t = 0.f;
#pragma unroll
        for (int i = 0; i < 8; i++) t += red[i];
        red[0] = t;
    }
    __syncthreads();
    const float inv = 1.f / red[0];

#pragma unroll 8
    for (int it = 0; it < nIter; it++) {
        const int idx = it * 256 + tid;
        s[idx] = m[it] ? 0.f : v[it] * inv;
    }
}

// ---------------- layernorm + residual (x <- LN(a)*g+b + x) ----------------
__global__ __launch_bounds__(256) void ln_res_kernel(
    const float* __restrict__ attn, float* __restrict__ x,
    const float* __restrict__ gamma, const float* __restrict__ beta)
{
    const int warp = threadIdx.x >> 5;
    const int lane = threadIdx.x & 31;
    const long row = (long)blockIdx.x * 8 + warp;
    const float* a = attn + row * HD;
    float* xr = x + row * HD;

    float v[8];
    {
        float4 v0 = *reinterpret_cast<const float4*>(a + lane * 8);
        float4 v1 = *reinterpret_cast<const float4*>(a + lane * 8 + 4);
        v[0] = v0.x; v[1] = v0.y; v[2] = v0.z; v[3] = v0.w;
        v[4] = v1.x; v[5] = v1.y; v[6] = v1.z; v[7] = v1.w;
    }
    float s = 0.f;
#pragma unroll
    for (int i = 0; i < 8; i++) s += v[i];
#pragma unroll
    for (int o = 16; o > 0; o >>= 1) s += __shfl_xor_sync(0xffffffffu, s, o);
    const float mu = s * (1.f / HD);

    float sq = 0.f;
#pragma unroll
    for (int i = 0; i < 8; i++) {
        float d = v[i] - mu;
        sq = fmaf(d, d, sq);
    }
#pragma unroll
    for (int o = 16; o > 0; o >>= 1) sq += __shfl_xor_sync(0xffffffffu, sq, o);
    const float r = rsqrtf(sq * (1.f / HD) + 1e-5f);

    float4 x0 = *reinterpret_cast<const float4*>(xr + lane * 8);
    float4 x1 = *reinterpret_cast<const float4*>(xr + lane * 8 + 4);
    float xin[8] = {x0.x, x0.y, x0.z, x0.w, x1.x, x1.y, x1.z, x1.w};

    float out[8];
#pragma unroll
    for (int i = 0; i < 8; i++) {
        const int col = lane * 8 + i;
        out[i] = (v[i] - mu) * r * gamma[col] + beta[col] + xin[i];
    }
    float4 o0 = {out[0], out[1], out[2], out[3]};
    float4 o1 = {out[4], out[5], out[6], out[7]};
    *reinterpret_cast<float4*>(xr + lane * 8) = o0;
    *reinterpret_cast<float4*>(xr + lane * 8 + 4) = o1;
}

// ---------------- final: out = future + x ----------------------------------
__global__ __launch_bounds__(256) void final_add(
    const float* __restrict__ fut, const float* __restrict__ x,
    float* __restrict__ o, int n4)
{
    const int i = blockIdx.x * blockDim.x + threadIdx.x;
    if (i < n4) {
        float4 a = reinterpret_cast<const float4*>(fut)[i];
        float4 b = reinterpret_cast<const float4*>(x)[i];
        float4 c = {a.x + b.x, a.y + b.y, a.z + b.z, a.w + b.w};
        reinterpret_cast<float4*>(o)[i] = c;
    }
}

// ---------------------------------------------------------------------------
extern "C" void kernel_launch(void* const* d_in, const int* in_sizes, int n_in,
                              void* d_out, int out_size)
{
    const float* future  = (const float*)d_in[0];
    const float* history = (const float*)d_in[1];
    const float* graph   = (const float*)d_in[2];
    const int*   mask_hf = (const int*)d_in[3];    // bool -> int32 per harness
    const int*   mask_fg = (const int*)d_in[4];
    const float* Wq      = (const float*)d_in[5];
    const float* bq      = (const float*)d_in[6];
    const float* Wk      = (const float*)d_in[7];
    const float* bk      = (const float*)d_in[8];
    const float* Wv      = (const float*)d_in[9];
    const float* bv      = (const float*)d_in[10];
    const float* gamma   = (const float*)d_in[11];
    const float* beta    = (const float*)d_in[12];
    float* out = (float*)d_out;

    float *px, *pq, *pk, *pv, *ps, *pa, *pweff, *pbeff, *pwtmp;
    cudaGetSymbolAddress((void**)&px,    g_x);
    cudaGetSymbolAddress((void**)&pq,    g_q);
    cudaGetSymbolAddress((void**)&pk,    g_k);
    cudaGetSymbolAddress((void**)&pv,    g_v);
    cudaGetSymbolAddress((void**)&ps,    g_s);
    cudaGetSymbolAddress((void**)&pa,    g_a);
    cudaGetSymbolAddress((void**)&pweff, g_weff);
    cudaGetSymbolAddress((void**)&pbeff, g_beff);
    cudaGetSymbolAddress((void**)&pwtmp, g_wtmp);

    // ---- collapse the 3 stacked affine layers: Weff = W0@W1@W2 -------------
    const float* Wbase[3] = {Wq, Wk, Wv};
    for (int t = 0; t < 3; t++) {
        const float* W = Wbase[t];
        dim3 g(HD / 64, HD / 64, 4);  // batched over layers l
        gemm64<<<g, 256>>>(W, W + HD * HD, nullptr, pwtmp,
                           HD, HD, HD, 1.f,
                           (long)3 * HD * HD, (long)3 * HD * HD, (long)HD * HD, 0);
        gemm64<<<g, 256>>>(pwtmp, W + 2 * HD * HD, nullptr,
                           pweff + (size_t)t * 4 * HD * HD,
                           HD, HD, HD, 1.f,
                           (long)HD * HD, (long)3 * HD * HD, (long)HD * HD, 0);
    }
    bias_collapse<<<12, 256>>>(bq, bk, bv, Wq, Wk, Wv, pbeff);

    // ---- x = future ---------------------------------------------------------
    cudaMemcpyAsync(px, future, sizeof(float) * NB * NFQ * HD,
                    cudaMemcpyDeviceToDevice, 0);

    // ---- 4 attention layers --------------------------------------------------
    for (int l = 0; l < 4; l++) {
        const float* x2   = (l < 2) ? history : graph;
        const int    Nk   = (l < 2) ? NFQ : NGK;
        const int*   mask = (l < 2) ? mask_hf : mask_fg;

        const float* Weq = pweff + (size_t)(0 * 4 + l) * HD * HD;
        const float* Wek = pweff + (size_t)(1 * 4 + l) * HD * HD;
        const float* Wev = pweff + (size_t)(2 * 4 + l) * HD * HD;
        const float* beq = pbeff + (size_t)(0 * 4 + l) * HD;
        const float* bek = pbeff + (size_t)(1 * 4 + l) * HD;
        const float* bev = pbeff + (size_t)(2 * 4 + l) * HD;

        // projections (collapsed to a single GEMM each)
        {
            dim3 gq(HD / 64, (NB * NFQ) / 64, 1);
            gemm64<<<gq, 256>>>(px, Weq, beq, pq, NB * NFQ, HD, HD, 1.f, 0, 0, 0, 0);
            dim3 gk(HD / 64, (NB * Nk) / 64, 1);
            gemm64<<<gk, 256>>>(x2, Wek, bek, pk, NB * Nk, HD, HD, 1.f, 0, 0, 0, 0);
            gemm64<<<gk, 256>>>(x2, Wev, bev, pv, NB * Nk, HD, HD, 1.f, 0, 0, 0, 0);
        }

        // scores = Q @ K^T / 16 (batched over B)
        {
            dim3 gs(Nk / 64, NFQ / 64, NB);
            gemm64<<<gs, 256>>>(pq, pk, nullptr, ps, NFQ, Nk, HD, 0.0625f,
                                (long)NFQ * HD, (long)Nk * HD, (long)NFQ * Nk, 1);
        }

        // masked softmax (in place)
        softmax_mask_kernel<<<NB * NFQ, 256>>>(ps, mask, Nk);

        // attn = W @ V (batched over B)
        {
            dim3 go(HD / 64, NFQ / 64, NB);
            gemm64<<<go, 256>>>(ps, pv, nullptr, pa, NFQ, HD, Nk, 1.f,
                                (long)NFQ * Nk, (long)Nk * HD, (long)NFQ * HD, 0);
        }

        // x = LN(attn)*gamma + beta + x
        ln_res_kernel<<<(NB * NFQ) / 8, 256>>>(pa, px, gamma + l * HD, beta + l * HD);
    }

    // ---- out = future + x ----------------------------------------------------
    const int n4 = NB * NFQ * HD / 4;
    final_add<<<(n4 + 255) / 256, 256>>>(future, px, out, n4);
}

// round 5
// speedup vs baseline: 2.5276x; 2.5276x over previous
#include <cuda_runtime.h>
#include <cuda_bf16.h>
#include <stdint.h>

#define HD 256
#define NB 16
#define NFQ 1024
#define NGK 2048

// ---------------- scratch (device globals; no allocation allowed) ----------
static __device__ float g_x[NB * NFQ * HD];            //  16 MB current x
static __device__ float g_q[NB * NFQ * HD];            //  16 MB
static __device__ float g_k[NB * NGK * HD];            //  33 MB
static __device__ float g_v[NB * NGK * HD];            //  33 MB V^T [B][H][Nk]
static __device__ float g_s[(size_t)NB * NFQ * NGK];   // 134 MB scores
static __device__ float g_a[NB * NFQ * HD];            //  16 MB attn out
static __device__ float g_wt[12 * HD * HD];            // collapsed W^T [t*4+l][n][k]
static __device__ float g_beff[12 * HD];               // collapsed biases
static __device__ float g_wtmp[12 * HD * HD];          // W0@W1 temp

// =================== helpers =================================================
__device__ __forceinline__ uint32_t smem_u32(const void* p) {
    uint32_t a;
    asm("{ .reg .u64 t; cvta.to.shared.u64 t, %1; cvt.u32.u64 %0, t; }" : "=r"(a) : "l"(p));
    return a;
}
#define SW128(o) ((o) ^ (((o) >> 3) & 0x70))

__device__ __forceinline__ void bsplit(float x, float y, uint32_t& h, uint32_t& l) {
    __nv_bfloat162 hh = __floats2bfloat162_rn(x, y);
    float2 back = __bfloat1622float2(hh);
    __nv_bfloat162 ll = __floats2bfloat162_rn(x - back.x, y - back.y);
    h = *reinterpret_cast<uint32_t*>(&hh);
    l = *reinterpret_cast<uint32_t*>(&ll);
}
__device__ __forceinline__ void st64(uint32_t a, uint32_t x, uint32_t y) {
    asm volatile("st.shared.v2.b32 [%0], {%1,%2};" :: "r"(a), "r"(x), "r"(y) : "memory");
}
__device__ __forceinline__ void ldsm4(uint32_t addr, uint32_t& r0, uint32_t& r1,
                                      uint32_t& r2, uint32_t& r3) {
    asm volatile("ldmatrix.sync.aligned.m8n8.x4.shared.b16 {%0,%1,%2,%3}, [%4];"
                 : "=r"(r0), "=r"(r1), "=r"(r2), "=r"(r3) : "r"(addr));
}
__device__ __forceinline__ void mma16816(float* c, const uint32_t* a,
                                         uint32_t b0, uint32_t b1) {
    asm volatile(
        "mma.sync.aligned.m16n8k16.row.col.f32.bf16.bf16.f32 "
        "{%0,%1,%2,%3}, {%4,%5,%6,%7}, {%8,%9}, {%0,%1,%2,%3};"
        : "+f"(c[0]), "+f"(c[1]), "+f"(c[2]), "+f"(c[3])
        : "r"(a[0]), "r"(a[1]), "r"(a[2]), "r"(a[3]), "r"(b0), "r"(b1));
}
// swizzled address of (row, 16B-unit) in a 128B-per-row tile
__device__ __forceinline__ uint32_t swaddr(uint32_t base, int row, int unit) {
    uint32_t b = (uint32_t)(row * 128 + unit * 16);
    return base + (b ^ ((b >> 3) & 0x70));
}

// smem layout (dynamic, 48KB): Ah[128x64 bf16]=16KB, Al=16KB, Bh[64x64]=8KB, Bl=8KB
#define OFF_AH 0u
#define OFF_AL 16384u
#define OFF_BH 32768u
#define OFF_BL 40960u
#define SMEM_BYTES 49152

// =================== tensor-core GEMM: D[M,N] = alpha*A@B^T + bias ==========
// A[M,K], B[N,K] fp32 K-major. CTA tile 128x64, K-chunk 64, bf16 hi/lo x3.
// transLd==0: C row-major (ld=N). transLd=R: C[b*N*R + n*R + r], b=m/R, r=m%R.
__global__ __launch_bounds__(256, 2) void gemm_mma(
    const float* __restrict__ A, const float* __restrict__ Bm,
    const float* __restrict__ bias, float* __restrict__ C,
    int N, int K, float alpha,
    long batchA, long batchB, long batchC, int transLd)
{
    extern __shared__ char smem[];
    const uint32_t sb = smem_u32(smem);
    const int tid = threadIdx.x;
    const int wid = tid >> 5;
    const int lane = tid & 31;
    const int m0 = blockIdx.y * 128;
    const int n0 = blockIdx.x * 64;
    A  += (long)blockIdx.z * batchA;
    Bm += (long)blockIdx.z * batchB;
    C  += (long)blockIdx.z * batchC;

    const int wm = wid & 3;        // warp m: 0..3 -> rows wm*32
    const int wn = wid >> 2;       // warp n: 0..1 -> cols wn*32
    const int m0w = wm * 32;
    const int n0w = wn * 32;

    float acc[2][4][4];
#pragma unroll
    for (int i = 0; i < 2; i++)
#pragma unroll
        for (int j = 0; j < 4; j++)
#pragma unroll
            for (int r = 0; r < 4; r++) acc[i][j][r] = 0.f;

    // ldmatrix lane address components
    const int lmat = lane >> 3, lr8 = lane & 7;
    // A x4: row = base + (mat&1)*8 + r8, unit = ks*2 + (mat>>1)
    const int aRowOff = (lmat & 1) * 8 + lr8;
    const int aUnitOff = lmat >> 1;
    // B x4: row = base + (mat>>1)*8 + r8, unit = ks*2 + (mat&1)
    const int bRowOff = (lmat >> 1) * 8 + lr8;
    const int bUnitOff = lmat & 1;

    const int nCh = K >> 6;
    for (int ch = 0; ch < nCh; ++ch) {
        const int k0 = ch << 6;
        // ---- load + split A (128x64) and B (64x64) ----
#pragma unroll
        for (int it = 0; it < 8; ++it) {
            const int idx = tid + it * 256;          // 0..2047
            const int r = idx >> 4, c4 = idx & 15;
            float4 f = *reinterpret_cast<const float4*>(
                A + (long)(m0 + r) * K + k0 + c4 * 4);
            uint32_t h0, l0, h1, l1;
            bsplit(f.x, f.y, h0, l0);
            bsplit(f.z, f.w, h1, l1);
            const uint32_t off = SW128((uint32_t)(r * 128 + c4 * 8));
            st64(sb + OFF_AH + off, h0, h1);
            st64(sb + OFF_AL + off, l0, l1);
        }
#pragma unroll
        for (int it = 0; it < 4; ++it) {
            const int idx = tid + it * 256;          // 0..1023
            const int r = idx >> 4, c4 = idx & 15;
            float4 f = *reinterpret_cast<const float4*>(
                Bm + (long)(n0 + r) * K + k0 + c4 * 4);
            uint32_t h0, l0, h1, l1;
            bsplit(f.x, f.y, h0, l0);
            bsplit(f.z, f.w, h1, l1);
            const uint32_t off = SW128((uint32_t)(r * 128 + c4 * 8));
            st64(sb + OFF_BH + off, h0, h1);
            st64(sb + OFF_BL + off, l0, l1);
        }
        __syncthreads();

        // ---- compute ----
#pragma unroll
        for (int ks = 0; ks < 4; ++ks) {
            uint32_t af[2][4], bb[2][4], blf[2][4];
            // A-hi frags (2 m16 tiles)
#pragma unroll
            for (int mi = 0; mi < 2; ++mi)
                ldsm4(swaddr(sb + OFF_AH, m0w + mi * 16 + aRowOff, ks * 2 + aUnitOff),
                      af[mi][0], af[mi][1], af[mi][2], af[mi][3]);
            // B-hi frags (2 n16 groups -> 4 n8 tiles)
#pragma unroll
            for (int g = 0; g < 2; ++g)
                ldsm4(swaddr(sb + OFF_BH, n0w + g * 16 + bRowOff, ks * 2 + bUnitOff),
                      bb[g][0], bb[g][1], bb[g][2], bb[g][3]);
            // ah * bh
#pragma unroll
            for (int mi = 0; mi < 2; ++mi)
#pragma unroll
                for (int nj = 0; nj < 4; ++nj) {
                    const int g = nj >> 1, p = (nj & 1) * 2;
                    mma16816(acc[mi][nj], af[mi], bb[g][p], bb[g][p + 1]);
                }
            // B-lo frags
#pragma unroll
            for (int g = 0; g < 2; ++g)
                ldsm4(swaddr(sb + OFF_BL, n0w + g * 16 + bRowOff, ks * 2 + bUnitOff),
                      blf[g][0], blf[g][1], blf[g][2], blf[g][3]);
            // ah * bl
#pragma unroll
            for (int mi = 0; mi < 2; ++mi)
#pragma unroll
                for (int nj = 0; nj < 4; ++nj) {
                    const int g = nj >> 1, p = (nj & 1) * 2;
                    mma16816(acc[mi][nj], af[mi], blf[g][p], blf[g][p + 1]);
                }
            // A-lo frags (reuse af)
#pragma unroll
            for (int mi = 0; mi < 2; ++mi)
                ldsm4(swaddr(sb + OFF_AL, m0w + mi * 16 + aRowOff, ks * 2 + aUnitOff),
                      af[mi][0], af[mi][1], af[mi][2], af[mi][3]);
            // al * bh
#pragma unroll
            for (int mi = 0; mi < 2; ++mi)
#pragma unroll
                for (int nj = 0; nj < 4; ++nj) {
                    const int g = nj >> 1, p = (nj & 1) * 2;
                    mma16816(acc[mi][nj], af[mi], bb[g][p], bb[g][p + 1]);
                }
        }
        __syncthreads();
    }

    // ---- epilogue ----
    const int qrow = lane >> 2;
    const int qcol = (lane & 3) * 2;
#pragma unroll
    for (int mi = 0; mi < 2; ++mi) {
#pragma unroll
        for (int nj = 0; nj < 4; ++nj) {
            const int col = n0 + n0w + nj * 8 + qcol;
            const int r0 = m0 + m0w + mi * 16 + qrow;
            const int r1 = r0 + 8;
            float c0 = acc[mi][nj][0] * alpha;
            float c1 = acc[mi][nj][1] * alpha;
            float c2 = acc[mi][nj][2] * alpha;
            float c3 = acc[mi][nj][3] * alpha;
            if (bias) {
                float b0 = bias[col], b1 = bias[col + 1];
                c0 += b0; c1 += b1; c2 += b0; c3 += b1;
            }
            if (transLd == 0) {
                float2 p0 = {c0, c1};
                float2 p1 = {c2, c3};
                *reinterpret_cast<float2*>(C + (long)r0 * N + col) = p0;
                *reinterpret_cast<float2*>(C + (long)r1 * N + col) = p1;
            } else {
                const int R = transLd;
                const int b0i = r0 / R, rr0 = r0 - b0i * R;
                const int b1i = r1 / R, rr1 = r1 - b1i * R;
                float* base0 = C + (long)b0i * ((long)N * R) + rr0;
                float* base1 = C + (long)b1i * ((long)N * R) + rr1;
                base0[(long)col * R] = c0;
                base0[(long)(col + 1) * R] = c1;
                base1[(long)col * R] = c2;
                base1[(long)(col + 1) * R] = c3;
            }
        }
    }
}

// =================== weight collapse (fp32 SIMT, tiny) ======================
__global__ __launch_bounds__(256) void wstage(
    const float* __restrict__ Wq, const float* __restrict__ Wk,
    const float* __restrict__ Wv,
    float* __restrict__ wtmp, float* __restrict__ wt, int stage)
{
    __shared__ __align__(16) float As[16][64];
    __shared__ __align__(16) float Bs[16][64];
    const int z = blockIdx.z, t = z >> 2, l = z & 3;
    const float* Wsel = (t == 0 ? Wq : (t == 1 ? Wk : Wv)) + (size_t)l * 3 * HD * HD;
    const float* A;
    const float* B;
    if (stage == 0) { A = Wsel; B = Wsel + HD * HD; }
    else            { A = wtmp + (size_t)z * HD * HD; B = Wsel + 2 * HD * HD; }

    const int tid = threadIdx.x;
    const int tx = tid & 15, ty = tid >> 4;
    const int m0 = blockIdx.y * 64, n0 = blockIdx.x * 64;
    float acc[4][4] = {};
    const int a_row = tid >> 2, a_cg = tid & 3;
    const int b_row = tid >> 4, b_cg = tid & 15;
    for (int k0 = 0; k0 < HD; k0 += 16) {
        float4 av = *reinterpret_cast<const float4*>(A + (m0 + a_row) * HD + k0 + a_cg * 4);
        As[a_cg * 4 + 0][a_row] = av.x;
        As[a_cg * 4 + 1][a_row] = av.y;
        As[a_cg * 4 + 2][a_row] = av.z;
        As[a_cg * 4 + 3][a_row] = av.w;
        float4 bv = *reinterpret_cast<const float4*>(B + (k0 + b_row) * HD + n0 + b_cg * 4);
        *reinterpret_cast<float4*>(&Bs[b_row][b_cg * 4]) = bv;
        __syncthreads();
#pragma unroll
        for (int kk = 0; kk < 16; kk++) {
            float4 a = *reinterpret_cast<const float4*>(&As[kk][ty << 2]);
            float4 b = *reinterpret_cast<const float4*>(&Bs[kk][tx << 2]);
            float ar[4] = {a.x, a.y, a.z, a.w};
            float br[4] = {b.x, b.y, b.z, b.w};
#pragma unroll
            for (int i = 0; i < 4; i++)
#pragma unroll
                for (int j = 0; j < 4; j++) acc[i][j] = fmaf(ar[i], br[j], acc[i][j]);
        }
        __syncthreads();
    }
    if (stage == 0) {
        float* Cc = wtmp + (size_t)z * HD * HD;
#pragma unroll
        for (int i = 0; i < 4; i++) {
            float4 o = {acc[i][0], acc[i][1], acc[i][2], acc[i][3]};
            *reinterpret_cast<float4*>(Cc + (m0 + ty * 4 + i) * HD + n0 + tx * 4) = o;
        }
    } else {
        float* Cc = wt + (size_t)z * HD * HD;
#pragma unroll
        for (int i = 0; i < 4; i++)
#pragma unroll
            for (int j = 0; j < 4; j++)
                Cc[(n0 + tx * 4 + j) * HD + (m0 + ty * 4 + i)] = acc[i][j];
    }
}

// ---------------- bias collapse: beff = (b0@W1 + b1)@W2 + b2 ---------------
__global__ __launch_bounds__(256) void bias_collapse(
    const float* __restrict__ bq, const float* __restrict__ bk,
    const float* __restrict__ bv,
    const float* __restrict__ Wq, const float* __restrict__ Wk,
    const float* __restrict__ Wv,
    float* __restrict__ beff)
{
    const int t = blockIdx.x >> 2;
    const int l = blockIdx.x & 3;
    const float* bb = (t == 0 ? bq : (t == 1 ? bk : bv)) + (size_t)l * 3 * HD;
    const float* WW = (t == 0 ? Wq : (t == 1 ? Wk : Wv)) + (size_t)l * 3 * HD * HD;
    const int n = threadIdx.x;
    __shared__ float tmp[HD];

    float s = bb[HD + n];
    for (int k = 0; k < HD; k++)
        s = fmaf(bb[k], WW[HD * HD + k * HD + n], s);
    tmp[n] = s;
    __syncthreads();
    float s2 = bb[2 * HD + n];
    for (int k = 0; k < HD; k++)
        s2 = fmaf(tmp[k], WW[2 * HD * HD + k * HD + n], s2);
    beff[(size_t)blockIdx.x * HD + n] = s2;
}

// ---------------- masked softmax (mask int32; exact ref semantics) ----------
__global__ __launch_bounds__(256) void softmax_mask_kernel(
    float* __restrict__ S, const int* __restrict__ mask, int Nk)
{
    const long row = blockIdx.x;
    float* s = S + row * (long)Nk;
    const int* mk = mask + row * (long)Nk;
    const int tid = threadIdx.x;
    const int nIter = Nk >> 8;

    float v[8];
    int m[8];
    float vmax = -3.0e38f;
#pragma unroll 8
    for (int it = 0; it < nIter; it++) {
        const int idx = it * 256 + tid;
        float sv = s[idx];
        int mm = mk[idx];
        sv = mm ? -1e12f : sv;
        v[it] = sv;
        m[it] = mm;
        vmax = fmaxf(vmax, sv);
    }
    __shared__ float red[8];
#pragma unroll
    for (int o = 16; o > 0; o >>= 1)
        vmax = fmaxf(vmax, __shfl_xor_sync(0xffffffffu, vmax, o));
    if ((tid & 31) == 0) red[tid >> 5] = vmax;
    __syncthreads();
    if (tid == 0) {
        float t = red[0];
#pragma unroll
        for (int i = 1; i < 8; i++) t = fmaxf(t, red[i]);
        red[0] = t;
    }
    __syncthreads();
    vmax = red[0];
    __syncthreads();

    float sum = 0.f;
#pragma unroll 8
    for (int it = 0; it < nIter; it++) {
        float e = __expf(v[it] - vmax);
        v[it] = e;
        sum += e;
    }
#pragma unroll
    for (int o = 16; o > 0; o >>= 1)
        sum += __shfl_xor_sync(0xffffffffu, sum, o);
    if ((tid & 31) == 0) red[tid >> 5] = sum;
    __syncthreads();
    if (tid == 0) {
        float t = 0.f;
#pragma unroll
        for (int i = 0; i < 8; i++) t += red[i];
        red[0] = t;
    }
    __syncthreads();
    const float inv = 1.f / red[0];
#pragma unroll 8
    for (int it = 0; it < nIter; it++) {
        const int idx = it * 256 + tid;
        s[idx] = m[it] ? 0.f : v[it] * inv;
    }
}

// ---------------- layernorm + residual --------------------------------------
__global__ __launch_bounds__(256) void ln_res_kernel(
    const float* __restrict__ attn, float* __restrict__ x,
    const float* __restrict__ gamma, const float* __restrict__ beta)
{
    const int warp = threadIdx.x >> 5;
    const int lane = threadIdx.x & 31;
    const long row = (long)blockIdx.x * 8 + warp;
    const float* a = attn + row * HD;
    float* xr = x + row * HD;

    float v[8];
    {
        float4 v0 = *reinterpret_cast<const float4*>(a + lane * 8);
        float4 v1 = *reinterpret_cast<const float4*>(a + lane * 8 + 4);
        v[0] = v0.x; v[1] = v0.y; v[2] = v0.z; v[3] = v0.w;
        v[4] = v1.x; v[5] = v1.y; v[6] = v1.z; v[7] = v1.w;
    }
    float s = 0.f;
#pragma unroll
    for (int i = 0; i < 8; i++) s += v[i];
#pragma unroll
    for (int o = 16; o > 0; o >>= 1) s += __shfl_xor_sync(0xffffffffu, s, o);
    const float mu = s * (1.f / HD);

    float sq = 0.f;
#pragma unroll
    for (int i = 0; i < 8; i++) {
        float d = v[i] - mu;
        sq = fmaf(d, d, sq);
    }
#pragma unroll
    for (int o = 16; o > 0; o >>= 1) sq += __shfl_xor_sync(0xffffffffu, sq, o);
    const float r = rsqrtf(sq * (1.f / HD) + 1e-5f);

    float4 x0 = *reinterpret_cast<const float4*>(xr + lane * 8);
    float4 x1 = *reinterpret_cast<const float4*>(xr + lane * 8 + 4);
    float xin[8] = {x0.x, x0.y, x0.z, x0.w, x1.x, x1.y, x1.z, x1.w};

    float out[8];
#pragma unroll
    for (int i = 0; i < 8; i++) {
        const int col = lane * 8 + i;
        out[i] = (v[i] - mu) * r * gamma[col] + beta[col] + xin[i];
    }
    float4 o0 = {out[0], out[1], out[2], out[3]};
    float4 o1 = {out[4], out[5], out[6], out[7]};
    *reinterpret_cast<float4*>(xr + lane * 8) = o0;
    *reinterpret_cast<float4*>(xr + lane * 8 + 4) = o1;
}

// ---------------- final: out = future + x ----------------------------------
__global__ __launch_bounds__(256) void final_add(
    const float* __restrict__ fut, const float* __restrict__ x,
    float* __restrict__ o, int n4)
{
    const int i = blockIdx.x * blockDim.x + threadIdx.x;
    if (i < n4) {
        float4 a = reinterpret_cast<const float4*>(fut)[i];
        float4 b = reinterpret_cast<const float4*>(x)[i];
        float4 c = {a.x + b.x, a.y + b.y, a.z + b.z, a.w + b.w};
        reinterpret_cast<float4*>(o)[i] = c;
    }
}

// ---------------------------------------------------------------------------
extern "C" void kernel_launch(void* const* d_in, const int* in_sizes, int n_in,
                              void* d_out, int out_size)
{
    const float* future  = (const float*)d_in[0];
    const float* history = (const float*)d_in[1];
    const float* graph   = (const float*)d_in[2];
    const int*   mask_hf = (const int*)d_in[3];
    const int*   mask_fg = (const int*)d_in[4];
    const float* Wq      = (const float*)d_in[5];
    const float* bq      = (const float*)d_in[6];
    const float* Wk      = (const float*)d_in[7];
    const float* bk      = (const float*)d_in[8];
    const float* Wv      = (const float*)d_in[9];
    const float* bv      = (const float*)d_in[10];
    const float* gamma   = (const float*)d_in[11];
    const float* beta    = (const float*)d_in[12];
    float* out = (float*)d_out;

    float *px, *pq, *pk, *pv, *ps, *pa, *pwt, *pbeff, *pwtmp;
    cudaGetSymbolAddress((void**)&px,    g_x);
    cudaGetSymbolAddress((void**)&pq,    g_q);
    cudaGetSymbolAddress((void**)&pk,    g_k);
    cudaGetSymbolAddress((void**)&pv,    g_v);
    cudaGetSymbolAddress((void**)&ps,    g_s);
    cudaGetSymbolAddress((void**)&pa,    g_a);
    cudaGetSymbolAddress((void**)&pwt,   g_wt);
    cudaGetSymbolAddress((void**)&pbeff, g_beff);
    cudaGetSymbolAddress((void**)&pwtmp, g_wtmp);

    // ---- collapse stacked affine layers (2 batched launches) ---------------
    wstage<<<dim3(4, 4, 12), 256>>>(Wq, Wk, Wv, pwtmp, pwt, 0);
    wstage<<<dim3(4, 4, 12), 256>>>(Wq, Wk, Wv, pwtmp, pwt, 1);
    bias_collapse<<<12, 256>>>(bq, bk, bv, Wq, Wk, Wv, pbeff);

    // ---- x = future ----------------------------------------------------------
    cudaMemcpyAsync(px, future, sizeof(float) * NB * NFQ * HD,
                    cudaMemcpyDeviceToDevice, 0);

    // ---- 4 attention layers ---------------------------------------------------
    for (int l = 0; l < 4; l++) {
        const float* x2   = (l < 2) ? history : graph;
        const int    Nk   = (l < 2) ? NFQ : NGK;
        const int*   mask = (l < 2) ? mask_hf : mask_fg;

        const float* Wtq = pwt + (size_t)(0 * 4 + l) * HD * HD;
        const float* Wtk = pwt + (size_t)(1 * 4 + l) * HD * HD;
        const float* Wtv = pwt + (size_t)(2 * 4 + l) * HD * HD;
        const float* beq = pbeff + (size_t)(0 * 4 + l) * HD;
        const float* bek = pbeff + (size_t)(1 * 4 + l) * HD;
        const float* bev = pbeff + (size_t)(2 * 4 + l) * HD;

        // projections: Q, K row-major; V stored transposed [B][H][Nk]
        gemm_mma<<<dim3(HD / 64, (NB * NFQ) / 128, 1), 256, SMEM_BYTES>>>(
            px, Wtq, beq, pq, HD, HD, 1.f, 0, 0, 0, 0);
        gemm_mma<<<dim3(HD / 64, (NB * Nk) / 128, 1), 256, SMEM_BYTES>>>(
            x2, Wtk, bek, pk, HD, HD, 1.f, 0, 0, 0, 0);
        gemm_mma<<<dim3(HD / 64, (NB * Nk) / 128, 1), 256, SMEM_BYTES>>>(
            x2, Wtv, bev, pv, HD, HD, 1.f, 0, 0, 0, Nk);

        // scores = Q @ K^T / 16, batched over B
        gemm_mma<<<dim3(Nk / 64, NFQ / 128, NB), 256, SMEM_BYTES>>>(
            pq, pk, nullptr, ps, Nk, HD, 0.0625f,
            (long)NFQ * HD, (long)Nk * HD, (long)NFQ * Nk, 0);

        // masked softmax (in place)
        softmax_mask_kernel<<<NB * NFQ, 256>>>(ps, mask, Nk);

        // attn = W @ V  (A = weights [NFQ,Nk], B = V^T [HD,Nk]), batched over B
        gemm_mma<<<dim3(HD / 64, NFQ / 128, NB), 256, SMEM_BYTES>>>(
            ps, pv, nullptr, pa, HD, Nk, 1.f,
            (long)NFQ * Nk, (long)HD * Nk, (long)NFQ * HD, 0);

        // x = LN(attn)*gamma + beta + x
        ln_res_kernel<<<(NB * NFQ) / 8, 256>>>(pa, px, gamma + l * HD, beta + l * HD);
    }

    // ---- out = future + x ------------------------------------------------------
    const int n4 = NB * NFQ * HD / 4;
    final_add<<<(n4 + 255) / 256, 256>>>(future, px, out, n4);
}

// round 6
// speedup vs baseline: 2.9754x; 1.1772x over previous
#include <cuda_runtime.h>
#include <cuda_bf16.h>
#include <stdint.h>

#define HD 256
#define NB 16
#define NFQ 1024
#define NGK 2048

typedef __nv_bfloat16 bf16;

// ---------------- scratch (device globals; no allocation allowed) ----------
static __device__ float g_x[NB * NFQ * HD];               // residual x (fp32)
static __device__ float g_s[(size_t)NB * NFQ * NGK];      // scores fp32 134MB
static __device__ float g_a[NB * NFQ * HD];               // attn out fp32
static __device__ bf16  g_xh[NB * NFQ * HD], g_xl[NB * NFQ * HD];
static __device__ bf16  g_hh[NB * NFQ * HD], g_hl[NB * NFQ * HD];   // history split
static __device__ bf16  g_gh[NB * NGK * HD], g_gl[NB * NGK * HD];   // graph split
static __device__ bf16  g_qh[NB * NFQ * HD], g_ql[NB * NFQ * HD];
static __device__ bf16  g_kh[NB * NGK * HD], g_kl[NB * NGK * HD];
static __device__ bf16  g_vh[NB * NGK * HD], g_vl[NB * NGK * HD];   // V^T [B][H][Nk]
static __device__ bf16  g_sh[(size_t)NB * NFQ * NGK];     // softmax weights hi
static __device__ bf16  g_sl[(size_t)NB * NFQ * NGK];     // softmax weights lo
static __device__ bf16  g_wth[12 * HD * HD], g_wtl[12 * HD * HD];   // W^T split
static __device__ float g_beff[12 * HD];
static __device__ float g_wtmp[12 * HD * HD];

// =================== helpers =================================================
__device__ __forceinline__ uint32_t smem_u32(const void* p) {
    uint32_t a;
    asm("{ .reg .u64 t; cvta.to.shared.u64 t, %1; cvt.u32.u64 %0, t; }" : "=r"(a) : "l"(p));
    return a;
}
#define SW128(o) ((o) ^ (((o) >> 3) & 0x70))

__device__ __forceinline__ void bsplit(float x, float y, uint32_t& h, uint32_t& l) {
    __nv_bfloat162 hh = __floats2bfloat162_rn(x, y);
    float2 back = __bfloat1622float2(hh);
    __nv_bfloat162 ll = __floats2bfloat162_rn(x - back.x, y - back.y);
    h = *reinterpret_cast<uint32_t*>(&hh);
    l = *reinterpret_cast<uint32_t*>(&ll);
}
__device__ __forceinline__ void ldsm4(uint32_t addr, uint32_t& r0, uint32_t& r1,
                                      uint32_t& r2, uint32_t& r3) {
    asm volatile("ldmatrix.sync.aligned.m8n8.x4.shared.b16 {%0,%1,%2,%3}, [%4];"
                 : "=r"(r0), "=r"(r1), "=r"(r2), "=r"(r3) : "r"(addr));
}
__device__ __forceinline__ void mma16816(float* c, const uint32_t* a,
                                         uint32_t b0, uint32_t b1) {
    asm volatile(
        "mma.sync.aligned.m16n8k16.row.col.f32.bf16.bf16.f32 "
        "{%0,%1,%2,%3}, {%4,%5,%6,%7}, {%8,%9}, {%0,%1,%2,%3};"
        : "+f"(c[0]), "+f"(c[1]), "+f"(c[2]), "+f"(c[3])
        : "r"(a[0]), "r"(a[1]), "r"(a[2]), "r"(a[3]), "r"(b0), "r"(b1));
}
__device__ __forceinline__ uint32_t swaddr(uint32_t base, int row, int unit) {
    uint32_t b = (uint32_t)(row * 128 + unit * 16);
    return base + (b ^ ((b >> 3) & 0x70));
}
__device__ __forceinline__ void cpa(uint32_t s, const bf16* g) {
    asm volatile("cp.async.cg.shared.global [%0], [%1], 16;"
                 :: "r"(s), "l"((uint64_t)__cvta_generic_to_global(g)) : "memory");
}

// smem per stage: Ah 16KB, Al 16KB, Bh 8KB, Bl 8KB = 48KB; 2 stages
#define OFF_AH 0u
#define OFF_AL 16384u
#define OFF_BH 32768u
#define OFF_BL 40960u
#define STAGE  49152u
#define SMEM_BYTES (2 * 49152)

// =================== bf16x3 tensor-core GEMM ================================
// D[M,N] = alpha*(Ah+Al)@(Bh+Bl)^T + bias.  A [M][K], B [N][K] bf16 K-major.
// CTA tile 128x64, K-chunk 64, cp.async double-buffered.
// Output: Cf!=0 -> fp32 row-major.  else bf16 hi/lo: transLd==0 row-major,
// transLd=R -> C[b*N*R + n*R + r], b=m/R, r=m%R.
__global__ __launch_bounds__(256, 2) void gemm_bf3(
    const bf16* __restrict__ Ah, const bf16* __restrict__ Al,
    const bf16* __restrict__ Bh, const bf16* __restrict__ Bl,
    const float* __restrict__ bias,
    float* __restrict__ Cf, bf16* __restrict__ Ch, bf16* __restrict__ Cl,
    int N, int K, float alpha,
    long batchA, long batchB, long batchC, int transLd)
{
    extern __shared__ char smem[];
    const uint32_t sb = smem_u32(smem);
    const int tid = threadIdx.x;
    const int wid = tid >> 5;
    const int lane = tid & 31;
    const int m0 = blockIdx.y * 128;
    const int n0 = blockIdx.x * 64;
    Ah += (long)blockIdx.z * batchA;
    Al += (long)blockIdx.z * batchA;
    Bh += (long)blockIdx.z * batchB;
    Bl += (long)blockIdx.z * batchB;

    const int wm = wid & 3;
    const int wn = wid >> 2;
    const int m0w = wm * 32;
    const int n0w = wn * 32;

    float acc[2][4][4];
#pragma unroll
    for (int i = 0; i < 2; i++)
#pragma unroll
        for (int j = 0; j < 4; j++)
#pragma unroll
            for (int r = 0; r < 4; r++) acc[i][j][r] = 0.f;

    const int lmat = lane >> 3, lr8 = lane & 7;
    const int aRowOff = (lmat & 1) * 8 + lr8;
    const int aUnitOff = lmat >> 1;
    const int bRowOff = (lmat >> 1) * 8 + lr8;
    const int bUnitOff = lmat & 1;

    const int nCh = K >> 6;

    auto issue = [&](int c) {
        const int k0 = c << 6;
        const uint32_t st = sb + (uint32_t)(c & 1) * STAGE;
#pragma unroll
        for (int i = 0; i < 4; ++i) {
            const int idx = tid + (i << 8);
            const int row = idx >> 3, un = idx & 7;
            const uint32_t so = SW128((uint32_t)(row * 128 + un * 16));
            const long go = (long)(m0 + row) * K + k0 + un * 8;
            cpa(st + OFF_AH + so, Ah + go);
            cpa(st + OFF_AL + so, Al + go);
        }
#pragma unroll
        for (int i = 0; i < 2; ++i) {
            const int idx = tid + (i << 8);
            const int row = idx >> 3, un = idx & 7;
            const uint32_t so = SW128((uint32_t)(row * 128 + un * 16));
            const long go = (long)(n0 + row) * K + k0 + un * 8;
            cpa(st + OFF_BH + so, Bh + go);
            cpa(st + OFF_BL + so, Bl + go);
        }
        asm volatile("cp.async.commit_group;" ::: "memory");
    };

    issue(0);
    for (int c = 0; c < nCh; ++c) {
        if (c + 1 < nCh) {
            issue(c + 1);
            asm volatile("cp.async.wait_group 1;" ::: "memory");
        } else {
            asm volatile("cp.async.wait_group 0;" ::: "memory");
        }
        __syncthreads();
        const uint32_t st = sb + (uint32_t)(c & 1) * STAGE;
#pragma unroll
        for (int ks = 0; ks < 4; ++ks) {
            uint32_t af[2][4], bh_[2][4], bl_[2][4];
#pragma unroll
            for (int mi = 0; mi < 2; ++mi)
                ldsm4(swaddr(st + OFF_AH, m0w + mi * 16 + aRowOff, ks * 2 + aUnitOff),
                      af[mi][0], af[mi][1], af[mi][2], af[mi][3]);
#pragma unroll
            for (int g = 0; g < 2; ++g)
                ldsm4(swaddr(st + OFF_BH, n0w + g * 16 + bRowOff, ks * 2 + bUnitOff),
                      bh_[g][0], bh_[g][1], bh_[g][2], bh_[g][3]);
#pragma unroll
            for (int mi = 0; mi < 2; ++mi)
#pragma unroll
                for (int nj = 0; nj < 4; ++nj) {
                    const int g = nj >> 1, p = (nj & 1) * 2;
                    mma16816(acc[mi][nj], af[mi], bh_[g][p], bh_[g][p + 1]);
                }
#pragma unroll
            for (int g = 0; g < 2; ++g)
                ldsm4(swaddr(st + OFF_BL, n0w + g * 16 + bRowOff, ks * 2 + bUnitOff),
                      bl_[g][0], bl_[g][1], bl_[g][2], bl_[g][3]);
#pragma unroll
            for (int mi = 0; mi < 2; ++mi)
#pragma unroll
                for (int nj = 0; nj < 4; ++nj) {
                    const int g = nj >> 1, p = (nj & 1) * 2;
                    mma16816(acc[mi][nj], af[mi], bl_[g][p], bl_[g][p + 1]);
                }
#pragma unroll
            for (int mi = 0; mi < 2; ++mi)
                ldsm4(swaddr(st + OFF_AL, m0w + mi * 16 + aRowOff, ks * 2 + aUnitOff),
                      af[mi][0], af[mi][1], af[mi][2], af[mi][3]);
#pragma unroll
            for (int mi = 0; mi < 2; ++mi)
#pragma unroll
                for (int nj = 0; nj < 4; ++nj) {
                    const int g = nj >> 1, p = (nj & 1) * 2;
                    mma16816(acc[mi][nj], af[mi], bh_[g][p], bh_[g][p + 1]);
                }
        }
        __syncthreads();
    }

    // ---- epilogue ----
    const int qrow = lane >> 2;
    const int qcol = (lane & 3) * 2;
#pragma unroll
    for (int mi = 0; mi < 2; ++mi) {
#pragma unroll
        for (int nj = 0; nj < 4; ++nj) {
            const int col = n0 + n0w + nj * 8 + qcol;
            const int r0 = m0 + m0w + mi * 16 + qrow;
            const int r1 = r0 + 8;
            float c0 = acc[mi][nj][0] * alpha;
            float c1 = acc[mi][nj][1] * alpha;
            float c2 = acc[mi][nj][2] * alpha;
            float c3 = acc[mi][nj][3] * alpha;
            if (bias) {
                float b0 = bias[col], b1 = bias[col + 1];
                c0 += b0; c1 += b1; c2 += b0; c3 += b1;
            }
            if (Cf) {
                float* base = Cf + (long)blockIdx.z * batchC;
                float2 p0 = {c0, c1};
                float2 p1 = {c2, c3};
                *reinterpret_cast<float2*>(base + (long)r0 * N + col) = p0;
                *reinterpret_cast<float2*>(base + (long)r1 * N + col) = p1;
            } else if (transLd == 0) {
                uint32_t h, l;
                bsplit(c0, c1, h, l);
                const long o0 = ((long)r0 * N + col) >> 1;
                reinterpret_cast<uint32_t*>(Ch)[o0] = h;
                reinterpret_cast<uint32_t*>(Cl)[o0] = l;
                bsplit(c2, c3, h, l);
                const long o1 = ((long)r1 * N + col) >> 1;
                reinterpret_cast<uint32_t*>(Ch)[o1] = h;
                reinterpret_cast<uint32_t*>(Cl)[o1] = l;
            } else {
                const int R = transLd;
                const int b0i = r0 / R, rr0 = r0 - b0i * R;
                const int b1i = r1 / R, rr1 = r1 - b1i * R;
                const long base0 = (long)b0i * N * R + rr0;
                const long base1 = (long)b1i * N * R + rr1;
                float vals[4] = {c0, c1, c2, c3};
                long offs[4] = {base0 + (long)col * R, base0 + (long)(col + 1) * R,
                                base1 + (long)col * R, base1 + (long)(col + 1) * R};
#pragma unroll
                for (int t = 0; t < 4; ++t) {
                    bf16 h = __float2bfloat16(vals[t]);
                    bf16 lo = __float2bfloat16(vals[t] - __bfloat162float(h));
                    Ch[offs[t]] = h;
                    Cl[offs[t]] = lo;
                }
            }
        }
    }
}

// =================== weight collapse ========================================
// stage 0: wtmp[z] = W[z][0] @ W[z][1]
// stage 1: wt[z] = (wtmp[z] @ W[z][2])^T  -> bf16 hi/lo [n][k]
__global__ __launch_bounds__(256) void wstage(
    const float* __restrict__ Wq, const float* __restrict__ Wk,
    const float* __restrict__ Wv,
    float* __restrict__ wtmp, bf16* __restrict__ wth, bf16* __restrict__ wtl,
    int stage)
{
    __shared__ __align__(16) float As[16][64];
    __shared__ __align__(16) float Bs[16][64];
    const int z = blockIdx.z, t = z >> 2, l = z & 3;
    const float* Wsel = (t == 0 ? Wq : (t == 1 ? Wk : Wv)) + (size_t)l * 3 * HD * HD;
    const float* A;
    const float* B;
    if (stage == 0) { A = Wsel; B = Wsel + HD * HD; }
    else            { A = wtmp + (size_t)z * HD * HD; B = Wsel + 2 * HD * HD; }

    const int tid = threadIdx.x;
    const int tx = tid & 15, ty = tid >> 4;
    const int m0 = blockIdx.y * 64, n0 = blockIdx.x * 64;
    float acc[4][4] = {};
    const int a_row = tid >> 2, a_cg = tid & 3;
    const int b_row = tid >> 4, b_cg = tid & 15;
    for (int k0 = 0; k0 < HD; k0 += 16) {
        float4 av = *reinterpret_cast<const float4*>(A + (m0 + a_row) * HD + k0 + a_cg * 4);
        As[a_cg * 4 + 0][a_row] = av.x;
        As[a_cg * 4 + 1][a_row] = av.y;
        As[a_cg * 4 + 2][a_row] = av.z;
        As[a_cg * 4 + 3][a_row] = av.w;
        float4 bv = *reinterpret_cast<const float4*>(B + (k0 + b_row) * HD + n0 + b_cg * 4);
        *reinterpret_cast<float4*>(&Bs[b_row][b_cg * 4]) = bv;
        __syncthreads();
#pragma unroll
        for (int kk = 0; kk < 16; kk++) {
            float4 a = *reinterpret_cast<const float4*>(&As[kk][ty << 2]);
            float4 b = *reinterpret_cast<const float4*>(&Bs[kk][tx << 2]);
            float ar[4] = {a.x, a.y, a.z, a.w};
            float br[4] = {b.x, b.y, b.z, b.w};
#pragma unroll
            for (int i = 0; i < 4; i++)
#pragma unroll
                for (int j = 0; j < 4; j++) acc[i][j] = fmaf(ar[i], br[j], acc[i][j]);
        }
        __syncthreads();
    }
    if (stage == 0) {
        float* Cc = wtmp + (size_t)z * HD * HD;
#pragma unroll
        for (int i = 0; i < 4; i++) {
            float4 o = {acc[i][0], acc[i][1], acc[i][2], acc[i][3]};
            *reinterpret_cast<float4*>(Cc + (m0 + ty * 4 + i) * HD + n0 + tx * 4) = o;
        }
    } else {
        bf16* Ch = wth + (size_t)z * HD * HD;
        bf16* Cl = wtl + (size_t)z * HD * HD;
#pragma unroll
        for (int i = 0; i < 4; i++)
#pragma unroll
            for (int j = 0; j < 4; j++) {
                const int n = n0 + tx * 4 + j, k = m0 + ty * 4 + i;
                float v = acc[i][j];
                bf16 h = __float2bfloat16(v);
                bf16 lo = __float2bfloat16(v - __bfloat162float(h));
                Ch[(size_t)n * HD + k] = h;
                Cl[(size_t)n * HD + k] = lo;
            }
    }
}

// ---------------- bias collapse: beff = (b0@W1 + b1)@W2 + b2 ---------------
__global__ __launch_bounds__(256) void bias_collapse(
    const float* __restrict__ bq, const float* __restrict__ bk,
    const float* __restrict__ bv,
    const float* __restrict__ Wq, const float* __restrict__ Wk,
    const float* __restrict__ Wv,
    float* __restrict__ beff)
{
    const int t = blockIdx.x >> 2;
    const int l = blockIdx.x & 3;
    const float* bb = (t == 0 ? bq : (t == 1 ? bk : bv)) + (size_t)l * 3 * HD;
    const float* WW = (t == 0 ? Wq : (t == 1 ? Wk : Wv)) + (size_t)l * 3 * HD * HD;
    const int n = threadIdx.x;
    __shared__ float tmp[HD];

    float s = bb[HD + n];
    for (int k = 0; k < HD; k++)
        s = fmaf(bb[k], WW[HD * HD + k * HD + n], s);
    tmp[n] = s;
    __syncthreads();
    float s2 = bb[2 * HD + n];
    for (int k = 0; k < HD; k++)
        s2 = fmaf(tmp[k], WW[2 * HD * HD + k * HD + n], s2);
    beff[(size_t)blockIdx.x * HD + n] = s2;
}

// ---------------- fp32 -> bf16 hi/lo split ----------------------------------
__global__ __launch_bounds__(256) void split_kernel(
    const float* __restrict__ src, bf16* __restrict__ h, bf16* __restrict__ l,
    int n2)
{
    const int i = blockIdx.x * 256 + threadIdx.x;
    if (i < n2) {
        float2 f = reinterpret_cast<const float2*>(src)[i];
        uint32_t hh, ll;
        bsplit(f.x, f.y, hh, ll);
        reinterpret_cast<uint32_t*>(h)[i] = hh;
        reinterpret_cast<uint32_t*>(l)[i] = ll;
    }
}

// ---------------- masked softmax -> bf16 hi/lo weights ----------------------
__global__ __launch_bounds__(256) void softmax_mask_kernel(
    const float* __restrict__ S, const int* __restrict__ mask,
    bf16* __restrict__ Sh, bf16* __restrict__ Sl, int Nk)
{
    const long row = blockIdx.x;
    const float2* s2 = reinterpret_cast<const float2*>(S + row * (long)Nk);
    const int2* mk2 = reinterpret_cast<const int2*>(mask + row * (long)Nk);
    const int tid = threadIdx.x;
    const int nIter = Nk >> 9;  // 2 or 4

    float2 v[4];
    int2 m[4];
    float vmax = -3.0e38f;
#pragma unroll 4
    for (int it = 0; it < nIter; it++) {
        const int idx = it * 256 + tid;
        float2 sv = s2[idx];
        int2 mm = mk2[idx];
        sv.x = mm.x ? -1e12f : sv.x;
        sv.y = mm.y ? -1e12f : sv.y;
        v[it] = sv;
        m[it] = mm;
        vmax = fmaxf(vmax, fmaxf(sv.x, sv.y));
    }
    __shared__ float red[8];
#pragma unroll
    for (int o = 16; o > 0; o >>= 1)
        vmax = fmaxf(vmax, __shfl_xor_sync(0xffffffffu, vmax, o));
    if ((tid & 31) == 0) red[tid >> 5] = vmax;
    __syncthreads();
    if (tid == 0) {
        float t = red[0];
#pragma unroll
        for (int i = 1; i < 8; i++) t = fmaxf(t, red[i]);
        red[0] = t;
    }
    __syncthreads();
    vmax = red[0];
    __syncthreads();

    float sum = 0.f;
#pragma unroll 4
    for (int it = 0; it < nIter; it++) {
        float ex = __expf(v[it].x - vmax);
        float ey = __expf(v[it].y - vmax);
        v[it].x = ex; v[it].y = ey;
        sum += ex + ey;
    }
#pragma unroll
    for (int o = 16; o > 0; o >>= 1)
        sum += __shfl_xor_sync(0xffffffffu, sum, o);
    if ((tid & 31) == 0) red[tid >> 5] = sum;
    __syncthreads();
    if (tid == 0) {
        float t = 0.f;
#pragma unroll
        for (int i = 0; i < 8; i++) t += red[i];
        red[0] = t;
    }
    __syncthreads();
    const float inv = 1.f / red[0];

    uint32_t* oh = reinterpret_cast<uint32_t*>(Sh) + row * (Nk >> 1);
    uint32_t* ol = reinterpret_cast<uint32_t*>(Sl) + row * (Nk >> 1);
#pragma unroll 4
    for (int it = 0; it < nIter; it++) {
        const int idx = it * 256 + tid;
        float w0 = m[it].x ? 0.f : v[it].x * inv;
        float w1 = m[it].y ? 0.f : v[it].y * inv;
        uint32_t hh, ll;
        bsplit(w0, w1, hh, ll);
        oh[idx] = hh;
        ol[idx] = ll;
    }
}

// ---------------- layernorm + residual; emits split x -----------------------
__global__ __launch_bounds__(256) void ln_res_kernel(
    const float* __restrict__ attn, float* __restrict__ x,
    bf16* __restrict__ xh, bf16* __restrict__ xl,
    const float* __restrict__ gamma, const float* __restrict__ beta)
{
    const int warp = threadIdx.x >> 5;
    const int lane = threadIdx.x & 31;
    const long row = (long)blockIdx.x * 8 + warp;
    const float* a = attn + row * HD;
    float* xr = x + row * HD;

    float v[8];
    {
        float4 v0 = *reinterpret_cast<const float4*>(a + lane * 8);
        float4 v1 = *reinterpret_cast<const float4*>(a + lane * 8 + 4);
        v[0] = v0.x; v[1] = v0.y; v[2] = v0.z; v[3] = v0.w;
        v[4] = v1.x; v[5] = v1.y; v[6] = v1.z; v[7] = v1.w;
    }
    float s = 0.f;
#pragma unroll
    for (int i = 0; i < 8; i++) s += v[i];
#pragma unroll
    for (int o = 16; o > 0; o >>= 1) s += __shfl_xor_sync(0xffffffffu, s, o);
    const float mu = s * (1.f / HD);

    float sq = 0.f;
#pragma unroll
    for (int i = 0; i < 8; i++) {
        float d = v[i] - mu;
        sq = fmaf(d, d, sq);
    }
#pragma unroll
    for (int o = 16; o > 0; o >>= 1) sq += __shfl_xor_sync(0xffffffffu, sq, o);
    const float r = rsqrtf(sq * (1.f / HD) + 1e-5f);

    float4 x0 = *reinterpret_cast<const float4*>(xr + lane * 8);
    float4 x1 = *reinterpret_cast<const float4*>(xr + lane * 8 + 4);
    float xin[8] = {x0.x, x0.y, x0.z, x0.w, x1.x, x1.y, x1.z, x1.w};

    float out[8];
#pragma unroll
    for (int i = 0; i < 8; i++) {
        const int col = lane * 8 + i;
        out[i] = (v[i] - mu) * r * gamma[col] + beta[col] + xin[i];
    }
    float4 o0 = {out[0], out[1], out[2], out[3]};
    float4 o1 = {out[4], out[5], out[6], out[7]};
    *reinterpret_cast<float4*>(xr + lane * 8) = o0;
    *reinterpret_cast<float4*>(xr + lane * 8 + 4) = o1;

    uint32_t* ph = reinterpret_cast<uint32_t*>(xh) + row * (HD >> 1) + lane * 4;
    uint32_t* pl = reinterpret_cast<uint32_t*>(xl) + row * (HD >> 1) + lane * 4;
#pragma unroll
    for (int i = 0; i < 4; i++) {
        uint32_t hh, ll;
        bsplit(out[2 * i], out[2 * i + 1], hh, ll);
        ph[i] = hh;
        pl[i] = ll;
    }
}

// ---------------- final: out = future + x ----------------------------------
__global__ __launch_bounds__(256) void final_add(
    const float* __restrict__ fut, const float* __restrict__ x,
    float* __restrict__ o, int n4)
{
    const int i = blockIdx.x * blockDim.x + threadIdx.x;
    if (i < n4) {
        float4 a = reinterpret_cast<const float4*>(fut)[i];
        float4 b = reinterpret_cast<const float4*>(x)[i];
        float4 c = {a.x + b.x, a.y + b.y, a.z + b.z, a.w + b.w};
        reinterpret_cast<float4*>(o)[i] = c;
    }
}

// ---------------------------------------------------------------------------
extern "C" void kernel_launch(void* const* d_in, const int* in_sizes, int n_in,
                              void* d_out, int out_size)
{
    const float* future  = (const float*)d_in[0];
    const float* history = (const float*)d_in[1];
    const float* graph   = (const float*)d_in[2];
    const int*   mask_hf = (const int*)d_in[3];
    const int*   mask_fg = (const int*)d_in[4];
    const float* Wq      = (const float*)d_in[5];
    const float* bq      = (const float*)d_in[6];
    const float* Wk      = (const float*)d_in[7];
    const float* bk      = (const float*)d_in[8];
    const float* Wv      = (const float*)d_in[9];
    const float* bv      = (const float*)d_in[10];
    const float* gamma   = (const float*)d_in[11];
    const float* beta    = (const float*)d_in[12];
    float* out = (float*)d_out;

    float *px, *ps, *pa, *pbeff, *pwtmp;
    bf16 *pxh, *pxl, *phh, *phl, *pgh, *pgl, *pqh, *pql, *pkh, *pkl;
    bf16 *pvh, *pvl, *psh, *psl, *pwth, *pwtl;
    cudaGetSymbolAddress((void**)&px,    g_x);
    cudaGetSymbolAddress((void**)&ps,    g_s);
    cudaGetSymbolAddress((void**)&pa,    g_a);
    cudaGetSymbolAddress((void**)&pbeff, g_beff);
    cudaGetSymbolAddress((void**)&pwtmp, g_wtmp);
    cudaGetSymbolAddress((void**)&pxh,   g_xh);
    cudaGetSymbolAddress((void**)&pxl,   g_xl);
    cudaGetSymbolAddress((void**)&phh,   g_hh);
    cudaGetSymbolAddress((void**)&phl,   g_hl);
    cudaGetSymbolAddress((void**)&pgh,   g_gh);
    cudaGetSymbolAddress((void**)&pgl,   g_gl);
    cudaGetSymbolAddress((void**)&pqh,   g_qh);
    cudaGetSymbolAddress((void**)&pql,   g_ql);
    cudaGetSymbolAddress((void**)&pkh,   g_kh);
    cudaGetSymbolAddress((void**)&pkl,   g_kl);
    cudaGetSymbolAddress((void**)&pvh,   g_vh);
    cudaGetSymbolAddress((void**)&pvl,   g_vl);
    cudaGetSymbolAddress((void**)&psh,   g_sh);
    cudaGetSymbolAddress((void**)&psl,   g_sl);
    cudaGetSymbolAddress((void**)&pwth,  g_wth);
    cudaGetSymbolAddress((void**)&pwtl,  g_wtl);

    cudaFuncSetAttribute(gemm_bf3, cudaFuncAttributeMaxDynamicSharedMemorySize,
                         SMEM_BYTES);

    // ---- collapse stacked affine layers -------------------------------------
    wstage<<<dim3(4, 4, 12), 256>>>(Wq, Wk, Wv, pwtmp, pwth, pwtl, 0);
    wstage<<<dim3(4, 4, 12), 256>>>(Wq, Wk, Wv, pwtmp, pwth, pwtl, 1);
    bias_collapse<<<12, 256>>>(bq, bk, bv, Wq, Wk, Wv, pbeff);

    // ---- x = future; split inputs ------------------------------------------
    cudaMemcpyAsync(px, future, sizeof(float) * NB * NFQ * HD,
                    cudaMemcpyDeviceToDevice, 0);
    {
        const int n2f = NB * NFQ * HD / 2;
        const int n2g = NB * NGK * HD / 2;
        split_kernel<<<n2f / 256, 256>>>(future, pxh, pxl, n2f);
        split_kernel<<<n2f / 256, 256>>>(history, phh, phl, n2f);
        split_kernel<<<n2g / 256, 256>>>(graph, pgh, pgl, n2g);
    }

    // ---- 4 attention layers --------------------------------------------------
    for (int l = 0; l < 4; l++) {
        const bf16* x2h   = (l < 2) ? phh : pgh;
        const bf16* x2l   = (l < 2) ? phl : pgl;
        const int   Nk    = (l < 2) ? NFQ : NGK;
        const int*  mask  = (l < 2) ? mask_hf : mask_fg;

        const bf16* Wqh = pwth + (size_t)(0 * 4 + l) * HD * HD;
        const bf16* Wql = pwtl + (size_t)(0 * 4 + l) * HD * HD;
        const bf16* Wkh = pwth + (size_t)(1 * 4 + l) * HD * HD;
        const bf16* Wkl = pwtl + (size_t)(1 * 4 + l) * HD * HD;
        const bf16* Wvh = pwth + (size_t)(2 * 4 + l) * HD * HD;
        const bf16* Wvl = pwtl + (size_t)(2 * 4 + l) * HD * HD;
        const float* beq = pbeff + (size_t)(0 * 4 + l) * HD;
        const float* bek = pbeff + (size_t)(1 * 4 + l) * HD;
        const float* bev = pbeff + (size_t)(2 * 4 + l) * HD;

        // projections -> split bf16 outputs
        gemm_bf3<<<dim3(HD / 64, (NB * NFQ) / 128, 1), 256, SMEM_BYTES>>>(
            pxh, pxl, Wqh, Wql, beq, nullptr, pqh, pql, HD, HD, 1.f, 0, 0, 0, 0);
        gemm_bf3<<<dim3(HD / 64, (NB * Nk) / 128, 1), 256, SMEM_BYTES>>>(
            x2h, x2l, Wkh, Wkl, bek, nullptr, pkh, pkl, HD, HD, 1.f, 0, 0, 0, 0);
        gemm_bf3<<<dim3(HD / 64, (NB * Nk) / 128, 1), 256, SMEM_BYTES>>>(
            x2h, x2l, Wvh, Wvl, bev, nullptr, pvh, pvl, HD, HD, 1.f, 0, 0, 0, Nk);

        // scores = Q @ K^T / 16 (fp32), batched over B
        gemm_bf3<<<dim3(Nk / 64, NFQ / 128, NB), 256, SMEM_BYTES>>>(
            pqh, pql, pkh, pkl, nullptr, ps, nullptr, nullptr, Nk, HD, 0.0625f,
            (long)NFQ * HD, (long)Nk * HD, (long)NFQ * Nk, 0);

        // masked softmax -> split bf16 weights
        softmax_mask_kernel<<<NB * NFQ, 256>>>(ps, mask, psh, psl, Nk);

        // attn = W @ V  (A = weights, B = V^T), batched over B
        gemm_bf3<<<dim3(HD / 64, NFQ / 128, NB), 256, SMEM_BYTES>>>(
            psh, psl, pvh, pvl, nullptr, pa, nullptr, nullptr, HD, Nk, 1.f,
            (long)NFQ * Nk, (long)HD * Nk, (long)NFQ * HD, 0);

        // x = LN(attn)*gamma + beta + x; also emit split x
        ln_res_kernel<<<(NB * NFQ) / 8, 256>>>(pa, px, pxh, pxl,
                                               gamma + l * HD, beta + l * HD);
    }

    // ---- out = future + x ------------------------------------------------------
    const int n4 = NB * NFQ * HD / 4;
    final_add<<<(n4 + 255) / 256, 256>>>(future, px, out, n4);
}